// round 1
// baseline (speedup 1.0000x reference)
#include <cuda_runtime.h>
#include <cstdint>

#define BATCH 4
#define CCH 7
#define DD 32
#define HH 192
#define WW 192
#define DHW (DD*HH*WW)        // 1179648
#define NIDS 16
#define NSEG (BATCH*NIDS)     // 64
#define NBITS 17
#define NB (1<<NBITS)         // 131072 bins over e in [0,2]

// ---------------- device scratch (static; no allocation) ----------------
__device__ float g_se[(size_t)BATCH*3*DHW];      // spatial_emb, 56.6MB
__device__ float g_seed[(size_t)BATCH*DHW];      // sigmoid seed map, 18.9MB
__device__ double g_stats[NSEG][10];             // cnt, Sx,Sy,Sz, Ss0..2, Sq0..2
__device__ double g_bg[BATCH];                   // bg seed loss
__device__ double g_seedl[NSEG];                 // fg seed loss per (b,iid)
__device__ double g_instl[NSEG];                 // lovasz per (b,iid)
__device__ float g_params[NSEG][8];              // cx,cy,cz, ex,ey,ez, cnt, var
__device__ unsigned long long g_hist[(size_t)NSEG*NB];  // 64MB: hi32=n1, lo32=n0

// ---------------- K0: zero scratch ----------------
__global__ void zero_kernel() {
    size_t i = (size_t)blockIdx.x*blockDim.x + threadIdx.x;
    size_t stride = (size_t)gridDim.x*blockDim.x;
    ulonglong2* p = reinterpret_cast<ulonglong2*>(g_hist);
    const size_t n2 = (size_t)NSEG*NB/2;
    for (size_t j = i; j < n2; j += stride) p[j] = make_ulonglong2(0ULL, 0ULL);
    if (i < NSEG*10) (&g_stats[0][0])[i] = 0.0;
    if (i < BATCH) g_bg[i] = 0.0;
    if (i < NSEG) { g_seedl[i] = 0.0; g_instl[i] = 0.0; }
}

// ---------------- K1: preprocess + per-instance stats ----------------
__global__ void prep_kernel(const float* __restrict__ pred,
                            const int* __restrict__ inst,
                            const int* __restrict__ lab,
                            const float* __restrict__ xyzm) {
    __shared__ float s_acc[NIDS*10];
    __shared__ float s_bg;
    int tid = threadIdx.x;
    if (tid < NIDS*10) s_acc[tid] = 0.f;
    if (tid == 0) s_bg = 0.f;
    __syncthreads();

    const int bpb = DHW/256;               // 4608 blocks per batch (exact)
    int b = blockIdx.x / bpb;
    int v = (blockIdx.x % bpb)*256 + tid;

    size_t pbase = (size_t)b*CCH*DHW + v;
    float p0 = pred[pbase];
    float p1 = pred[pbase + (size_t)DHW];
    float p2 = pred[pbase + 2*(size_t)DHW];
    float s0 = pred[pbase + 3*(size_t)DHW];
    float s1 = pred[pbase + 4*(size_t)DHW];
    float s2 = pred[pbase + 5*(size_t)DHW];
    float p6 = pred[pbase + 6*(size_t)DHW];
    float x0 = xyzm[v];
    float x1 = xyzm[v + DHW];
    float x2 = xyzm[v + 2*DHW];

    float se0 = tanhf(p0) + x0;
    float se1 = tanhf(p1) + x1;
    float se2 = tanhf(p2) + x2;
    float sd  = 1.f/(1.f + __expf(-p6));

    size_t sbase = (size_t)b*3*DHW + v;
    g_se[sbase]           = se0;
    g_se[sbase + DHW]     = se1;
    g_se[sbase + 2*DHW]   = se2;
    g_seed[(size_t)b*DHW + v] = sd;

    int iv = inst[(size_t)b*DHW + v];
    int lv = lab[(size_t)b*DHW + v];
    if (lv == 0) atomicAdd(&s_bg, sd*sd);
    if (iv >= 1 && iv <= NIDS) {
        float* a = &s_acc[(iv-1)*10];
        atomicAdd(&a[0], 1.f);
        atomicAdd(&a[1], x0); atomicAdd(&a[2], x1); atomicAdd(&a[3], x2);
        atomicAdd(&a[4], s0); atomicAdd(&a[5], s1); atomicAdd(&a[6], s2);
        atomicAdd(&a[7], s0*s0); atomicAdd(&a[8], s1*s1); atomicAdd(&a[9], s2*s2);
    }
    __syncthreads();
    if (tid < NIDS*10) {
        float vsum = s_acc[tid];
        if (vsum != 0.f)
            atomicAdd(&(&g_stats[0][0])[(size_t)b*NIDS*10 + tid], (double)vsum);
    }
    if (tid == 0 && s_bg != 0.f) atomicAdd(&g_bg[b], (double)s_bg);
}

// ---------------- K2: finalize per-instance params ----------------
__global__ void finalize_stats_kernel() {
    int i = threadIdx.x;
    if (i >= NSEG) return;
    const double* s = g_stats[i];
    double cnt  = s[0];
    double safe = cnt > 1.0 ? cnt : 1.0;
    double inv  = 1.0/safe;
    double c0 = s[1]*inv, c1 = s[2]*inv, c2 = s[3]*inv;
    double m0 = s[4]*inv, m1 = s[5]*inv, m2 = s[6]*inv;
    double varnum = (s[7] - 2.0*m0*s[4] + m0*m0*cnt)
                  + (s[8] - 2.0*m1*s[5] + m1*m1*cnt)
                  + (s[9] - 2.0*m2*s[6] + m2*m2*cnt);
    double var = varnum/(3.0*safe);
    g_params[i][0] = (float)c0;
    g_params[i][1] = (float)c1;
    g_params[i][2] = (float)c2;
    g_params[i][3] = expf(10.f*(float)m0);
    g_params[i][4] = expf(10.f*(float)m1);
    g_params[i][5] = expf(10.f*(float)m2);
    g_params[i][6] = (float)cnt;
    g_params[i][7] = (float)var;
}

// ---------------- K3: dist + error histogram + fg seed loss ----------------
__global__ void hist_kernel(const int* __restrict__ inst) {
    __shared__ float s_p[NIDS*6];
    __shared__ float s_sl[NIDS];
    int tid = threadIdx.x;
    const int bpb = DHW/256;
    int b = blockIdx.x / bpb;
    int v = (blockIdx.x % bpb)*256 + tid;
    if (tid < NIDS*6) s_p[tid] = g_params[b*NIDS + tid/6][tid%6];
    if (tid < NIDS) s_sl[tid] = 0.f;
    __syncthreads();

    size_t sbase = (size_t)b*3*DHW + v;
    float se0 = g_se[sbase];
    float se1 = g_se[sbase + DHW];
    float se2 = g_se[sbase + 2*DHW];
    float sd  = g_seed[(size_t)b*DHW + v];
    int iv    = inst[(size_t)b*DHW + v];

    unsigned long long* hb = g_hist + (((size_t)b*NIDS) << NBITS);
    #pragma unroll
    for (int i = 0; i < NIDS; i++) {
        float d0 = se0 - s_p[i*6+0];
        float d1 = se1 - s_p[i*6+1];
        float d2 = se2 - s_p[i*6+2];
        float q  = d0*d0*s_p[i*6+3] + d1*d1*s_p[i*6+4] + d2*d2*s_p[i*6+5];
        float d  = __expf(-q);
        bool gt  = (iv == i+1);
        float e  = gt ? (2.f - 2.f*d) : (2.f*d);
        int bin  = (int)(e * (float)(NB/2));
        if (bin > NB-1) bin = NB-1;
        if (bin < 0) bin = 0;
        atomicAdd(&hb[((size_t)i << NBITS) + bin], gt ? (1ULL<<32) : 1ULL);
        if (gt) { float df = sd - d; atomicAdd(&s_sl[i], df*df); }
    }
    __syncthreads();
    if (tid < NIDS && s_sl[tid] != 0.f)
        atomicAdd(&g_seedl[b*NIDS + tid], (double)s_sl[tid]);
}

// ---------------- K4: Lovasz scan over histogram bins (descending e) ----------------
__global__ void lovasz_scan_kernel() {
    int seg = blockIdx.x;                      // (b,iid)
    const unsigned long long* hist = g_hist + ((size_t)seg << NBITS);
    float cntf = g_params[seg][6];
    int gts = (int)(cntf + 0.5f);
    if (gts == 0) return;                      // g_instl already zeroed

    __shared__ unsigned long long sh_w[32];
    __shared__ unsigned long long sh_carry;
    __shared__ double sred[32];
    int tid = threadIdx.x, lane = tid & 31, wid = tid >> 5;
    if (tid == 0) sh_carry = 0ULL;
    __syncthreads();

    double acc = 0.0;
    const double gtsd  = (double)gts;
    const double width = 2.0 / (double)NB;

    for (int chunk = 0; chunk < NB; chunk += 1024) {
        int pos = chunk + tid;                 // position in descending order
        int bin = NB - 1 - pos;
        unsigned long long hv = hist[bin];
        unsigned n1 = (unsigned)(hv >> 32);
        unsigned nt = n1 + (unsigned)hv;
        unsigned long long pack = ((unsigned long long)n1 << 32) | (unsigned long long)nt;

        // warp inclusive scan (u64)
        unsigned long long x = pack;
        #pragma unroll
        for (int off = 1; off < 32; off <<= 1) {
            unsigned long long y = __shfl_up_sync(0xffffffffu, x, off);
            if (lane >= off) x += y;
        }
        if (lane == 31) sh_w[wid] = x;
        unsigned long long carry = sh_carry;
        __syncthreads();
        if (wid == 0) {
            unsigned long long w = sh_w[lane];
            unsigned long long xx = w;
            #pragma unroll
            for (int off = 1; off < 32; off <<= 1) {
                unsigned long long y = __shfl_up_sync(0xffffffffu, xx, off);
                if (lane >= off) xx += y;
            }
            sh_w[lane] = xx - w;               // exclusive warp offset
            if (lane == 31) sh_carry = carry + xx;
        }
        __syncthreads();

        unsigned long long incl = x + sh_w[wid] + carry;
        unsigned long long excl = incl - pack;
        if (nt) {
            unsigned n1b = (unsigned)(excl >> 32);
            unsigned ntb = (unsigned)excl;
            unsigned cs_e = n1b + n1;
            unsigned nt_e = ntb + nt;
            // J before run (exclusive counts) and at end of run (inclusive)
            double Jb = 1.0 - (gtsd - (double)n1b)/(gtsd + (double)(ntb - n1b));
            double Je = 1.0 - (gtsd - (double)cs_e)/(gtsd + (double)(nt_e - cs_e));
            double e_rep = ((double)bin + 0.5) * width;
            acc += e_rep * (Je - Jb);
        }
        __syncthreads();                       // protect sh_w before next iter's writes
    }

    // block reduce (double)
    #pragma unroll
    for (int off = 16; off; off >>= 1) acc += __shfl_down_sync(0xffffffffu, acc, off);
    if (lane == 0) sred[wid] = acc;
    __syncthreads();
    if (wid == 0) {
        double a = (lane < 32) ? sred[lane] : 0.0;
        #pragma unroll
        for (int off = 16; off; off >>= 1) a += __shfl_down_sync(0xffffffffu, a, off);
        if (lane == 0) g_instl[seg] = a;
    }
}

// ---------------- K5: final combine ----------------
__global__ void final_kernel(float* __restrict__ out) {
    if (threadIdx.x != 0) return;
    float li = 0.f, lv = 0.f, ls = 0.f;
    for (int b = 0; b < BATCH; b++) {
        float obj = 0.f, vb = 0.f, ib = 0.f, sb = 0.f;
        for (int i = 0; i < NIDS; i++) {
            int s = b*NIDS + i;
            float cnt = g_params[s][6];
            if (cnt > 0.f) {
                obj += 1.f;
                vb += g_params[s][7];
                ib += (float)g_instl[s];
                sb += (float)g_seedl[s];
            }
        }
        float denom = obj > 1.f ? obj : 1.f;
        li += ib/denom;
        lv += vb/denom;
        ls += (sb + (float)g_bg[b]) / (float)DHW;
    }
    li = li * 1.0f / BATCH;          // W_INST
    lv = lv * 10.0f / BATCH;         // W_VAR
    ls = ls * 1.0f / BATCH;          // W_SEED
    out[0] = li; out[1] = lv; out[2] = ls; out[3] = li + lv + ls;
}

// ---------------- launch ----------------
extern "C" void kernel_launch(void* const* d_in, const int* in_sizes, int n_in,
                              void* d_out, int out_size) {
    const float* pred = (const float*)d_in[0];
    const int*   inst = (const int*)d_in[1];
    const int*   lab  = (const int*)d_in[2];
    // d_in[3] = center_images (unused by reference)
    const float* xyzm = (const float*)d_in[4];
    float* out = (float*)d_out;

    zero_kernel<<<8192, 256>>>();
    prep_kernel<<<BATCH*(DHW/256), 256>>>(pred, inst, lab, xyzm);
    finalize_stats_kernel<<<1, 64>>>();
    hist_kernel<<<BATCH*(DHW/256), 256>>>(inst);
    lovasz_scan_kernel<<<NSEG, 1024>>>();
    final_kernel<<<1, 32>>>(out);
}

// round 4
// speedup vs baseline: 1.5984x; 1.5984x over previous
#include <cuda_runtime.h>
#include <cstdint>

#define BATCH 4
#define CCH 7
#define DD 32
#define HH 192
#define WW 192
#define DHW (DD*HH*WW)        // 1179648
#define NIDS 16
#define NSEG (BATCH*NIDS)     // 64
#define NBITS 16
#define NB (1<<NBITS)         // 65536 bins over e in [0,2]

// ---------------- device scratch (static; BSS zero-init at load) ----------------
__device__ float g_se[(size_t)BATCH*3*DHW];      // spatial_emb
__device__ float g_seed[(size_t)BATCH*DHW];      // sigmoid seed map
__device__ double g_stats[NSEG][10];             // cnt, Sx,Sy,Sz, Ss0..2, Sq0..2 (self-zeroed by finalize)
__device__ double g_bg[BATCH];                   // bg seed loss (self-zeroed by final)
__device__ double g_seedl[NSEG];                 // fg seed loss (self-zeroed by final)
__device__ double g_instl[NSEG];                 // lovasz (overwritten by scan)
__device__ float g_params[NSEG][8];              // cx,cy,cz, ex,ey,ez, cnt, var
__device__ unsigned long long g_hist[(size_t)NSEG*NB];  // 32MB (self-zeroed by scan)

// ---------------- K1: preprocess + per-instance stats (per-warp privatized) ----------------
__global__ __launch_bounds__(1024) void prep_kernel(const float* __restrict__ pred,
                            const int* __restrict__ inst,
                            const int* __restrict__ lab,
                            const float* __restrict__ xyzm) {
    __shared__ float s_acc[32*16*11];            // 32 warps x 16 ids x stride 11
    __shared__ float s_bg;
    int tid = threadIdx.x;
    int lane = tid & 31, wid = tid >> 5;
    for (int i = tid; i < 32*16*11; i += 1024) s_acc[i] = 0.f;
    if (tid == 0) s_bg = 0.f;
    __syncthreads();

    const int bpb = DHW/1024;                    // 1152 blocks per batch (exact)
    int b = blockIdx.x / bpb;
    int v = (blockIdx.x % bpb)*1024 + tid;

    size_t pbase = (size_t)b*CCH*DHW + v;
    float p0 = pred[pbase];
    float p1 = pred[pbase + (size_t)DHW];
    float p2 = pred[pbase + 2*(size_t)DHW];
    float s0 = pred[pbase + 3*(size_t)DHW];
    float s1 = pred[pbase + 4*(size_t)DHW];
    float s2 = pred[pbase + 5*(size_t)DHW];
    float p6 = pred[pbase + 6*(size_t)DHW];
    float x0 = xyzm[v];
    float x1 = xyzm[v + DHW];
    float x2 = xyzm[v + 2*DHW];

    float se0 = tanhf(p0) + x0;
    float se1 = tanhf(p1) + x1;
    float se2 = tanhf(p2) + x2;
    float sd  = 1.f/(1.f + __expf(-p6));

    size_t sbase = (size_t)b*3*DHW + v;
    g_se[sbase]           = se0;
    g_se[sbase + DHW]     = se1;
    g_se[sbase + 2*DHW]   = se2;
    g_seed[(size_t)b*DHW + v] = sd;

    int iv = inst[(size_t)b*DHW + v];
    int lv = lab[(size_t)b*DHW + v];

    // bg seed: warp reduce then one shared atomic per warp
    float bgv = (lv == 0) ? sd*sd : 0.f;
    #pragma unroll
    for (int off = 16; off; off >>= 1) bgv += __shfl_down_sync(0xffffffffu, bgv, off);
    if (lane == 0 && bgv != 0.f) atomicAdd(&s_bg, bgv);

    if (iv >= 1 && iv <= NIDS) {
        float* a = &s_acc[(wid*16 + (iv-1))*11];
        atomicAdd(&a[0], 1.f);
        atomicAdd(&a[1], x0); atomicAdd(&a[2], x1); atomicAdd(&a[3], x2);
        atomicAdd(&a[4], s0); atomicAdd(&a[5], s1); atomicAdd(&a[6], s2);
        atomicAdd(&a[7], s0*s0); atomicAdd(&a[8], s1*s1); atomicAdd(&a[9], s2*s2);
    }
    __syncthreads();

    // flush: 160 values (16 ids x 10 stats), sum across 32 warps
    if (tid < 160) {
        int id = tid / 10, k = tid % 10;
        float vsum = 0.f;
        #pragma unroll
        for (int w = 0; w < 32; w++) vsum += s_acc[(w*16 + id)*11 + k];
        if (vsum != 0.f)
            atomicAdd(&g_stats[b*NIDS + id][k], (double)vsum);
    }
    if (tid == 0 && s_bg != 0.f) atomicAdd(&g_bg[b], (double)s_bg);
}

// ---------------- K2: finalize per-instance params (+ self-zero stats) ----------------
__global__ void finalize_stats_kernel() {
    int i = threadIdx.x;
    if (i >= NSEG) return;
    double s[10];
    #pragma unroll
    for (int k = 0; k < 10; k++) { s[k] = g_stats[i][k]; g_stats[i][k] = 0.0; }
    double cnt  = s[0];
    double safe = cnt > 1.0 ? cnt : 1.0;
    double inv  = 1.0/safe;
    double c0 = s[1]*inv, c1 = s[2]*inv, c2 = s[3]*inv;
    double m0 = s[4]*inv, m1 = s[5]*inv, m2 = s[6]*inv;
    double varnum = (s[7] - 2.0*m0*s[4] + m0*m0*cnt)
                  + (s[8] - 2.0*m1*s[5] + m1*m1*cnt)
                  + (s[9] - 2.0*m2*s[6] + m2*m2*cnt);
    double var = varnum/(3.0*safe);
    g_params[i][0] = (float)c0;
    g_params[i][1] = (float)c1;
    g_params[i][2] = (float)c2;
    g_params[i][3] = expf(10.f*(float)m0);
    g_params[i][4] = expf(10.f*(float)m1);
    g_params[i][5] = expf(10.f*(float)m2);
    g_params[i][6] = (float)cnt;
    g_params[i][7] = (float)var;
}

// ---------------- K3: dist + error histogram + fg seed loss ----------------
__global__ __launch_bounds__(256) void hist_kernel(const int* __restrict__ inst) {
    __shared__ float s_p[NIDS*6];
    __shared__ float s_sl[NIDS];
    int tid = threadIdx.x;
    const int bpb = DHW/256;
    int b = blockIdx.x / bpb;
    int v = (blockIdx.x % bpb)*256 + tid;
    if (tid < NIDS*6) s_p[tid] = g_params[b*NIDS + tid/6][tid%6];
    if (tid < NIDS) s_sl[tid] = 0.f;
    __syncthreads();

    size_t sbase = (size_t)b*3*DHW + v;
    float se0 = g_se[sbase];
    float se1 = g_se[sbase + DHW];
    float se2 = g_se[sbase + 2*DHW];
    float sd  = g_seed[(size_t)b*DHW + v];
    int iv    = inst[(size_t)b*DHW + v];

    unsigned long long* hb = g_hist + (((size_t)b*NIDS) << NBITS);
    #pragma unroll
    for (int i = 0; i < NIDS; i++) {
        float d0 = se0 - s_p[i*6+0];
        float d1 = se1 - s_p[i*6+1];
        float d2 = se2 - s_p[i*6+2];
        float q  = d0*d0*s_p[i*6+3] + d1*d1*s_p[i*6+4] + d2*d2*s_p[i*6+5];
        float d  = __expf(-q);
        bool gt  = (iv == i+1);
        float e  = gt ? (2.f - 2.f*d) : (2.f*d);
        int bin  = (int)(e * (float)(NB/2));
        if (bin > NB-1) bin = NB-1;
        if (bin < 0) bin = 0;
        atomicAdd(&hb[((size_t)i << NBITS) + bin], gt ? (1ULL<<32) : 1ULL);
        if (gt) { float df = sd - d; atomicAdd(&s_sl[i], df*df); }
    }
    __syncthreads();
    if (tid < NIDS && s_sl[tid] != 0.f)
        atomicAdd(&g_seedl[b*NIDS + tid], (double)s_sl[tid]);
}

// ---------------- K4: Lovasz over histogram (1 block-scan; self-zeroes hist) ----------------
__global__ __launch_bounds__(1024) void lovasz_scan_kernel() {
    int seg = blockIdx.x;                      // (b,iid)
    unsigned long long* hist = g_hist + ((size_t)seg << NBITS);
    int tid = threadIdx.x, lane = tid & 31, wid = tid >> 5;
    const int PER = NB/1024;                   // 64 bins per thread

    long long gts = (long long)(g_params[seg][6] + 0.5f);

    // Phase A: per-thread local sum over its 64 descending positions.
    // pack layout: hi32 = gt-count prefix, lo32 = total-count prefix
    int p0 = tid*PER;
    unsigned long long local = 0;
    #pragma unroll 4
    for (int j = 0; j < PER; j++) {
        unsigned long long hv = hist[NB-1-(p0+j)];
        local += hv + (hv >> 32);              // (n1<<32 | n0) -> (n1<<32 | n1+n0)
    }

    // Block exclusive scan of 1024 locals (in thread order = descending order)
    __shared__ unsigned long long sh_w[32];
    unsigned long long x = local;
    #pragma unroll
    for (int off = 1; off < 32; off <<= 1) {
        unsigned long long y = __shfl_up_sync(0xffffffffu, x, off);
        if (lane >= off) x += y;
    }
    if (lane == 31) sh_w[wid] = x;
    __syncthreads();
    if (wid == 0) {
        unsigned long long w = sh_w[lane];
        unsigned long long xx = w;
        #pragma unroll
        for (int off = 1; off < 32; off <<= 1) {
            unsigned long long y = __shfl_up_sync(0xffffffffu, xx, off);
            if (lane >= off) xx += y;
        }
        sh_w[lane] = xx - w;                   // exclusive warp offsets
    }
    __syncthreads();
    unsigned long long run = (x - local) + sh_w[wid];   // exclusive prefix for this thread

    // Phase B: walk own bins, accumulate lovasz contribution, zero hist behind us.
    double acc = 0.0;
    const float width = 2.0f / (float)NB;
    #pragma unroll 4
    for (int j = 0; j < PER; j++) {
        int bin = NB-1-(p0+j);
        unsigned long long hv = hist[bin];
        hist[bin] = 0ULL;                      // self-clean for next replay
        unsigned n1 = (unsigned)(hv >> 32);
        unsigned n0 = (unsigned)hv;
        unsigned nt = n1 + n0;
        if (nt) {
            long long n1b = (long long)(run >> 32);     // gt before this bin
            long long ntb = (long long)(unsigned)run;   // total before this bin
            long long interb = gts - n1b;
            long long unionb = gts + (ntb - n1b);       // gts + n0-prefix
            long long intere = interb - (long long)n1;
            long long unione = unionb + (long long)n0;
            // Je - Jb = interb/unionb - intere/unione, exact int64 cross product
            long long num = interb*unione - intere*unionb;
            long long den = unionb*unione;
            float e_rep = ((float)bin + 0.5f) * width;
            acc += (double)e_rep * ((double)num / (double)den);
            run += ((unsigned long long)n1 << 32) | (unsigned long long)nt;
        }
    }

    // block reduce (double)
    __shared__ double sred[32];
    #pragma unroll
    for (int off = 16; off; off >>= 1) acc += __shfl_down_sync(0xffffffffu, acc, off);
    if (lane == 0) sred[wid] = acc;
    __syncthreads();
    if (wid == 0) {
        double a = sred[lane];
        #pragma unroll
        for (int off = 16; off; off >>= 1) a += __shfl_down_sync(0xffffffffu, a, off);
        if (lane == 0) g_instl[seg] = (gts > 0) ? a : 0.0;
    }
}

// ---------------- K5: final combine (+ self-zero seedl/bg) ----------------
__global__ void final_kernel(float* __restrict__ out) {
    if (threadIdx.x != 0) return;
    float li = 0.f, lv = 0.f, ls = 0.f;
    for (int b = 0; b < BATCH; b++) {
        float obj = 0.f, vb = 0.f, ib = 0.f, sb = 0.f;
        for (int i = 0; i < NIDS; i++) {
            int s = b*NIDS + i;
            float cnt = g_params[s][6];
            if (cnt > 0.f) {
                obj += 1.f;
                vb += g_params[s][7];
                ib += (float)g_instl[s];
                sb += (float)g_seedl[s];
            }
            g_seedl[s] = 0.0;
        }
        float denom = obj > 1.f ? obj : 1.f;
        li += ib/denom;
        lv += vb/denom;
        ls += (sb + (float)g_bg[b]) / (float)DHW;
        g_bg[b] = 0.0;
    }
    li = li * 1.0f / BATCH;          // W_INST
    lv = lv * 10.0f / BATCH;         // W_VAR
    ls = ls * 1.0f / BATCH;          // W_SEED
    out[0] = li; out[1] = lv; out[2] = ls; out[3] = li + lv + ls;
}

// ---------------- launch ----------------
extern "C" void kernel_launch(void* const* d_in, const int* in_sizes, int n_in,
                              void* d_out, int out_size) {
    const float* pred = (const float*)d_in[0];
    const int*   inst = (const int*)d_in[1];
    const int*   lab  = (const int*)d_in[2];
    // d_in[3] = center_images (unused by reference)
    const float* xyzm = (const float*)d_in[4];
    float* out = (float*)d_out;

    prep_kernel<<<BATCH*(DHW/1024), 1024>>>(pred, inst, lab, xyzm);
    finalize_stats_kernel<<<1, 64>>>();
    hist_kernel<<<BATCH*(DHW/256), 256>>>(inst);
    lovasz_scan_kernel<<<NSEG, 1024>>>();
    final_kernel<<<1, 32>>>(out);
}

// round 5
// speedup vs baseline: 3.1369x; 1.9625x over previous
#include <cuda_runtime.h>
#include <cstdint>

#define BATCH 4
#define CCH 7
#define DD 32
#define HH 192
#define WW 192
#define DHW (DD*HH*WW)        // 1179648
#define NIDS 16
#define NSEG (BATCH*NIDS)     // 64
#define NBITS 16
#define NB (1<<NBITS)         // 65536 bins over e in [0,2]
#define NCH 64                // chunks per segment
#define CHUNK (NB/NCH)        // 1024 bins per chunk
#define ROUNDS (CHUNK/32)     // 32 warp rounds per chunk

typedef unsigned long long u64;

// ---------------- device scratch (static; BSS zero-init at load) ----------------
__device__ float g_se[(size_t)BATCH*3*DHW];      // spatial_emb
__device__ float g_seed[(size_t)BATCH*DHW];      // sigmoid seed map
__device__ double g_stats[NSEG][8];              // cnt, Sx,Sy,Sz, Ss0..2, SqT (self-zeroed by finalize)
__device__ double g_bg[BATCH];                   // bg seed loss (self-zeroed by final)
__device__ double g_seedl[NSEG];                 // fg seed loss (self-zeroed by final)
__device__ double g_instl[NSEG];                 // lovasz accum (self-zeroed by final)
__device__ float g_params[NSEG][8];              // cx,cy,cz, ex,ey,ez, cnt, var
__device__ u64 g_hist[(size_t)NSEG*NB];          // 32MB (self-zeroed by scan pass 2)
__device__ u64 g_csum[NSEG][NCH];                // per-chunk packed sums (overwritten each run)

// ---------------- K1: preprocess + per-instance stats (per-warp privatized) ----------------
__global__ __launch_bounds__(1024) void prep_kernel(const float* __restrict__ pred,
                            const int* __restrict__ inst,
                            const int* __restrict__ lab,
                            const float* __restrict__ xyzm) {
    __shared__ float s_acc[32*16*9];             // 32 warps x 16 ids x 8 stats (pad 9)
    __shared__ float s_bg;
    int tid = threadIdx.x;
    int lane = tid & 31, wid = tid >> 5;
    for (int i = tid; i < 32*16*9; i += 1024) s_acc[i] = 0.f;
    if (tid == 0) s_bg = 0.f;
    __syncthreads();

    const int bpb = DHW/1024;                    // 1152 blocks per batch (exact)
    int b = blockIdx.x / bpb;
    int v = (blockIdx.x % bpb)*1024 + tid;

    size_t pbase = (size_t)b*CCH*DHW + v;
    float p0 = pred[pbase];
    float p1 = pred[pbase + (size_t)DHW];
    float p2 = pred[pbase + 2*(size_t)DHW];
    float s0 = pred[pbase + 3*(size_t)DHW];
    float s1 = pred[pbase + 4*(size_t)DHW];
    float s2 = pred[pbase + 5*(size_t)DHW];
    float p6 = pred[pbase + 6*(size_t)DHW];
    float x0 = xyzm[v];
    float x1 = xyzm[v + DHW];
    float x2 = xyzm[v + 2*DHW];

    float se0 = tanhf(p0) + x0;
    float se1 = tanhf(p1) + x1;
    float se2 = tanhf(p2) + x2;
    float sd  = 1.f/(1.f + __expf(-p6));

    size_t sbase = (size_t)b*3*DHW + v;
    g_se[sbase]           = se0;
    g_se[sbase + DHW]     = se1;
    g_se[sbase + 2*DHW]   = se2;
    g_seed[(size_t)b*DHW + v] = sd;

    int iv = inst[(size_t)b*DHW + v];
    int lv = lab[(size_t)b*DHW + v];

    // bg seed: warp reduce then one shared atomic per warp
    float bgv = (lv == 0) ? sd*sd : 0.f;
    #pragma unroll
    for (int off = 16; off; off >>= 1) bgv += __shfl_down_sync(0xffffffffu, bgv, off);
    if (lane == 0 && bgv != 0.f) atomicAdd(&s_bg, bgv);

    if (iv >= 1 && iv <= NIDS) {
        float* a = &s_acc[(wid*16 + (iv-1))*9];
        atomicAdd(&a[0], 1.f);
        atomicAdd(&a[1], x0); atomicAdd(&a[2], x1); atomicAdd(&a[3], x2);
        atomicAdd(&a[4], s0); atomicAdd(&a[5], s1); atomicAdd(&a[6], s2);
        atomicAdd(&a[7], s0*s0 + s1*s1 + s2*s2);
    }
    __syncthreads();

    // flush: 128 values (16 ids x 8 stats), sum across 32 warps
    if (tid < 128) {
        int id = tid >> 3, k = tid & 7;
        float vsum = 0.f;
        #pragma unroll
        for (int w = 0; w < 32; w++) vsum += s_acc[(w*16 + id)*9 + k];
        if (vsum != 0.f)
            atomicAdd(&g_stats[b*NIDS + id][k], (double)vsum);
    }
    if (tid == 0 && s_bg != 0.f) atomicAdd(&g_bg[b], (double)s_bg);
}

// ---------------- K2: finalize per-instance params (+ self-zero stats) ----------------
__global__ void finalize_stats_kernel() {
    int i = threadIdx.x;
    if (i >= NSEG) return;
    double s[8];
    #pragma unroll
    for (int k = 0; k < 8; k++) { s[k] = g_stats[i][k]; g_stats[i][k] = 0.0; }
    double cnt  = s[0];
    double safe = cnt > 1.0 ? cnt : 1.0;
    double inv  = 1.0/safe;
    double c0 = s[1]*inv, c1 = s[2]*inv, c2 = s[3]*inv;
    double m0 = s[4]*inv, m1 = s[5]*inv, m2 = s[6]*inv;
    double varnum = s[7] - 2.0*(m0*s[4] + m1*s[5] + m2*s[6])
                  + (m0*m0 + m1*m1 + m2*m2)*cnt;
    double var = varnum/(3.0*safe);
    g_params[i][0] = (float)c0;
    g_params[i][1] = (float)c1;
    g_params[i][2] = (float)c2;
    g_params[i][3] = expf(10.f*(float)m0);
    g_params[i][4] = expf(10.f*(float)m1);
    g_params[i][5] = expf(10.f*(float)m2);
    g_params[i][6] = (float)cnt;
    g_params[i][7] = (float)var;
}

// ---------------- K3: dist + error histogram + fg seed loss ----------------
__global__ __launch_bounds__(256) void hist_kernel(const int* __restrict__ inst) {
    __shared__ float s_p[NIDS*6];
    __shared__ float s_sl[NIDS];
    int tid = threadIdx.x;
    const int bpb = DHW/256;
    int b = blockIdx.x / bpb;
    int v = (blockIdx.x % bpb)*256 + tid;
    if (tid < NIDS*6) s_p[tid] = g_params[b*NIDS + tid/6][tid%6];
    if (tid < NIDS) s_sl[tid] = 0.f;
    __syncthreads();

    size_t sbase = (size_t)b*3*DHW + v;
    float se0 = g_se[sbase];
    float se1 = g_se[sbase + DHW];
    float se2 = g_se[sbase + 2*DHW];
    float sd  = g_seed[(size_t)b*DHW + v];
    int iv    = inst[(size_t)b*DHW + v];

    u64* hb = g_hist + (((size_t)b*NIDS) << NBITS);
    #pragma unroll
    for (int i = 0; i < NIDS; i++) {
        float d0 = se0 - s_p[i*6+0];
        float d1 = se1 - s_p[i*6+1];
        float d2 = se2 - s_p[i*6+2];
        float q  = d0*d0*s_p[i*6+3] + d1*d1*s_p[i*6+4] + d2*d2*s_p[i*6+5];
        float d  = __expf(-q);
        bool gt  = (iv == i+1);
        float e  = gt ? (2.f - 2.f*d) : (2.f*d);
        int bin  = (int)(e * (float)(NB/2));
        if (bin > NB-1) bin = NB-1;
        if (bin < 0) bin = 0;
        atomicAdd(&hb[((size_t)i << NBITS) + bin], gt ? (1ULL<<32) : 1ULL);
        if (gt) { float df = sd - d; atomicAdd(&s_sl[i], df*df); }
    }
    __syncthreads();
    if (tid < NIDS && s_sl[tid] != 0.f)
        atomicAdd(&g_seedl[b*NIDS + tid], (double)s_sl[tid]);
}

// ---------------- K4a: per-chunk packed sums (coalesced) ----------------
// pack = (n1 << 32) | (n1+n0); chunk index runs over DESCENDING bin positions.
__global__ __launch_bounds__(256) void chunk_sum_kernel() {
    int lane = threadIdx.x & 31;
    int gw = blockIdx.x*8 + (threadIdx.x >> 5);  // global warp id, 4096 total
    int seg = gw >> 6;
    int ch  = gw & (NCH-1);
    const u64* hist = g_hist + ((size_t)seg << NBITS);
    int base = ch*CHUNK;                         // descending-position base
    u64 sum = 0;
    #pragma unroll 8
    for (int r = 0; r < ROUNDS; r++) {
        u64 hv = hist[NB-1 - (base + r*32 + lane)];
        sum += hv + (hv >> 32);
    }
    #pragma unroll
    for (int off = 16; off; off >>= 1)
        sum += __shfl_down_sync(0xffffffffu, sum, off);
    if (lane == 0) g_csum[seg][ch] = sum;
}

// ---------------- K4b: Lovasz main pass (coalesced, self-zeroes hist) ----------------
__global__ __launch_bounds__(256) void lovasz_scan_kernel() {
    int lane = threadIdx.x & 31;
    int gw = blockIdx.x*8 + (threadIdx.x >> 5);
    int seg = gw >> 6;
    int ch  = gw & (NCH-1);
    u64* hist = g_hist + ((size_t)seg << NBITS);
    long long gts = (long long)(g_params[seg][6] + 0.5f);

    // inter-chunk exclusive prefix: sum csum of chunks [0, ch)
    u64 pre = 0;
    if (lane < ch) pre = g_csum[seg][lane];
    if (lane + 32 < ch) pre += g_csum[seg][lane + 32];
    #pragma unroll
    for (int off = 16; off; off >>= 1)
        pre += __shfl_xor_sync(0xffffffffu, pre, off);
    u64 carry = pre;                             // same in all lanes

    int base = ch*CHUNK;
    double acc = 0.0;
    const float width = 2.0f / (float)NB;

    #pragma unroll 4
    for (int r = 0; r < ROUNDS; r++) {
        int bin = NB-1 - (base + r*32 + lane);
        u64 hv = hist[bin];
        hist[bin] = 0ULL;                        // self-clean for next replay
        u64 pack = hv + (hv >> 32);

        // inclusive warp scan (ascending lane = descending bin order)
        u64 x = pack;
        #pragma unroll
        for (int off = 1; off < 32; off <<= 1) {
            u64 y = __shfl_up_sync(0xffffffffu, x, off);
            if (lane >= off) x += y;
        }
        u64 tot = __shfl_sync(0xffffffffu, x, 31);
        u64 run = carry + x - pack;              // exclusive prefix for this bin
        carry += tot;

        unsigned n1 = (unsigned)(hv >> 32);
        unsigned n0 = (unsigned)hv;
        if (n1 + n0) {
            long long n1b = (long long)(run >> 32);     // gt before this bin
            long long ntb = (long long)(unsigned)run;   // total before this bin
            long long interb = gts - n1b;
            long long unionb = gts + (ntb - n1b);
            long long intere = interb - (long long)n1;
            long long unione = unionb + (long long)(n0 + n1) - (long long)n1;
            // Je - Jb = interb/unionb - intere/unione (exact int64 cross product)
            long long num = interb*unione - intere*unionb;
            long long den = unionb*unione;
            float e_rep = ((float)bin + 0.5f) * width;
            acc += (double)e_rep * ((double)num / (double)den);
        }
    }

    #pragma unroll
    for (int off = 16; off; off >>= 1)
        acc += __shfl_down_sync(0xffffffffu, acc, off);
    if (lane == 0 && gts > 0 && acc != 0.0)
        atomicAdd(&g_instl[seg], acc);
}

// ---------------- K5: final combine (+ self-zero accumulators) ----------------
__global__ void final_kernel(float* __restrict__ out) {
    if (threadIdx.x != 0) return;
    float li = 0.f, lv = 0.f, ls = 0.f;
    for (int b = 0; b < BATCH; b++) {
        float obj = 0.f, vb = 0.f, ib = 0.f, sb = 0.f;
        for (int i = 0; i < NIDS; i++) {
            int s = b*NIDS + i;
            float cnt = g_params[s][6];
            if (cnt > 0.f) {
                obj += 1.f;
                vb += g_params[s][7];
                ib += (float)g_instl[s];
                sb += (float)g_seedl[s];
            }
            g_seedl[s] = 0.0;
            g_instl[s] = 0.0;
        }
        float denom = obj > 1.f ? obj : 1.f;
        li += ib/denom;
        lv += vb/denom;
        ls += (sb + (float)g_bg[b]) / (float)DHW;
        g_bg[b] = 0.0;
    }
    li = li * 1.0f / BATCH;          // W_INST
    lv = lv * 10.0f / BATCH;         // W_VAR
    ls = ls * 1.0f / BATCH;          // W_SEED
    out[0] = li; out[1] = lv; out[2] = ls; out[3] = li + lv + ls;
}

// ---------------- launch ----------------
extern "C" void kernel_launch(void* const* d_in, const int* in_sizes, int n_in,
                              void* d_out, int out_size) {
    const float* pred = (const float*)d_in[0];
    const int*   inst = (const int*)d_in[1];
    const int*   lab  = (const int*)d_in[2];
    // d_in[3] = center_images (unused by reference)
    const float* xyzm = (const float*)d_in[4];
    float* out = (float*)d_out;

    prep_kernel<<<BATCH*(DHW/1024), 1024>>>(pred, inst, lab, xyzm);
    finalize_stats_kernel<<<1, 64>>>();
    hist_kernel<<<BATCH*(DHW/256), 256>>>(inst);
    chunk_sum_kernel<<<(NSEG*NCH)/8, 256>>>();
    lovasz_scan_kernel<<<(NSEG*NCH)/8, 256>>>();
    final_kernel<<<1, 32>>>(out);
}